// round 6
// baseline (speedup 1.0000x reference)
#include <cuda_runtime.h>
#include <cstdint>

#define D_MODEL 1024
#define NUM_HEADS 16
#define D_K 64
#define BATCH 4
#define SEQ 2048
#define BH (BATCH * NUM_HEADS)          // 64
#define M_ROWS (BATCH * SEQ)            // 8192

// Scratch (device globals; no dynamic allocation allowed)
__device__ float g_q[(size_t)BH * SEQ * D_K];
__device__ float g_k[(size_t)BH * SEQ * D_K];
__device__ float g_vt[(size_t)BH * D_K * SEQ];   // V transposed: [bh][d][s]
__device__ float g_ctx[(size_t)M_ROWS * D_MODEL];
__device__ float g_l[(size_t)BH * SEQ];          // softmax row sums
__device__ float g_attn_fb[(size_t)BH * SEQ * SEQ];

// Round fp32 -> tf32 (round-to-nearest; HMMA then truncates losslessly)
__device__ __forceinline__ uint32_t rn_tf32(float x) {
    return (__float_as_uint(x) + 0x1000u) & 0xFFFFE000u;
}
__device__ __forceinline__ float rn_tf32f(float x) {
    return __uint_as_float(rn_tf32(x));
}

__device__ __forceinline__ void mma_tf32(float* d, const uint32_t* a, const uint32_t* b) {
    asm volatile(
        "mma.sync.aligned.m16n8k8.row.col.f32.tf32.tf32.f32 "
        "{%0,%1,%2,%3}, {%4,%5,%6,%7}, {%8,%9}, {%0,%1,%2,%3};"
        : "+f"(d[0]), "+f"(d[1]), "+f"(d[2]), "+f"(d[3])
        : "r"(a[0]), "r"(a[1]), "r"(a[2]), "r"(a[3]), "r"(b[0]), "r"(b[1]));
}

// Fragment smem block strides (padded to break STS bank conflicts)
#define ABLK 132   // 128 floats + 4 pad
#define BBLK 66    // 64 floats + 2 pad

// ---------------------------------------------------------------------------
// Projection GEMM:  C = A(M x K, K-major) * B(N x K, K-major)^T   (tf32 MMA)
// Block tile 128 x 128, BK = 32, 256 threads, warps 4x2, 2 CTAs/SM.
// EPI: 0 = split-heads Q/K (+bias), 1 = V transposed (+bias), 2 = row-major (+bias)
// ---------------------------------------------------------------------------
template <int EPI>
__global__ void __launch_bounds__(256, 2) mma_gemm(
    const float* __restrict__ A, const float* __restrict__ B,
    const float* __restrict__ bias, float* __restrict__ C,
    int K, int lda, int ldb)
{
    constexpr int A_FLOATS = 32 * ABLK;   // ka4 x ma8 blocks
    constexpr int B_FLOATS = 64 * BBLK;   // ka4 x na16 blocks

    extern __shared__ float smf[];
    float* As = smf;
    float* Bs = smf + 2 * A_FLOATS;

    const int tid = threadIdx.x;
    const int wid = tid >> 5, lid = tid & 31;
    const int warp_m = wid >> 1, warp_n = wid & 1;
    const int bm = blockIdx.y * 128;
    const int bn = blockIdx.x * 128;

    const float* Ab = A + (size_t)bm * lda;
    const float* Bb = B + (size_t)bn * ldb;

    float4 ra[4], rb[4];

    auto ldg_tiles = [&](int k0) {
#pragma unroll
        for (int it = 0; it < 4; it++) {
            int f = tid + it * 256;
            int row = f >> 3, k4 = f & 7;
            ra[it] = *(const float4*)(Ab + (size_t)row * lda + k0 + k4 * 4);
            rb[it] = *(const float4*)(Bb + (size_t)row * ldb + k0 + k4 * 4);
        }
    };

    auto sts_tiles = [&](int buf) {
        float* da = As + buf * A_FLOATS;
        float* db = Bs + buf * B_FLOATS;
#pragma unroll
        for (int it = 0; it < 4; it++) {
            int f = tid + it * 256;
            int row = f >> 3, k4 = f & 7;
            {
                int ma = row >> 4, r = row & 15;
                int ka = k4 >> 1;
                int slot = ((k4 & 1) << 1) | (r >> 3);
                float* p = da + ((ka * 8 + ma) * ABLK + ((r & 7) << 4) + slot);
                p[0]  = __uint_as_float(rn_tf32(ra[it].x));
                p[4]  = __uint_as_float(rn_tf32(ra[it].y));
                p[8]  = __uint_as_float(rn_tf32(ra[it].z));
                p[12] = __uint_as_float(rn_tf32(ra[it].w));
            }
            {
                int na = row >> 3, nn = row & 7;
                int ka = k4 >> 1;
                int slot = k4 & 1;
                float* p = db + ((ka * 16 + na) * BBLK + (nn << 3) + slot);
                p[0] = __uint_as_float(rn_tf32(rb[it].x));
                p[2] = __uint_as_float(rn_tf32(rb[it].y));
                p[4] = __uint_as_float(rn_tf32(rb[it].z));
                p[6] = __uint_as_float(rn_tf32(rb[it].w));
            }
        }
    };

    float acc[2][8][4];
#pragma unroll
    for (int im = 0; im < 2; im++)
#pragma unroll
        for (int in = 0; in < 8; in++)
#pragma unroll
            for (int c = 0; c < 4; c++) acc[im][in][c] = 0.f;

    const int KS = K >> 5;
    ldg_tiles(0);
    sts_tiles(0);
    ldg_tiles(32);
    __syncthreads();

    for (int ks = 0; ks < KS; ks++) {
        if (ks + 1 < KS) sts_tiles((ks + 1) & 1);
        if (ks + 2 < KS) ldg_tiles((ks + 2) << 5);

        const float* Ad = As + (ks & 1) * A_FLOATS;
        const float* Bd = Bs + (ks & 1) * B_FLOATS;
#pragma unroll
        for (int ka = 0; ka < 4; ka++) {
            uint32_t afr[2][4];
#pragma unroll
            for (int im = 0; im < 2; im++) {
                const float4 v = *(const float4*)(Ad + (ka * 8 + warp_m * 2 + im) * ABLK + lid * 4);
                afr[im][0] = __float_as_uint(v.x); afr[im][1] = __float_as_uint(v.y);
                afr[im][2] = __float_as_uint(v.z); afr[im][3] = __float_as_uint(v.w);
            }
            uint32_t bfr[8][2];
#pragma unroll
            for (int in = 0; in < 8; in++) {
                const float2 v = *(const float2*)(Bd + (ka * 16 + warp_n * 8 + in) * BBLK + lid * 2);
                bfr[in][0] = __float_as_uint(v.x); bfr[in][1] = __float_as_uint(v.y);
            }
#pragma unroll
            for (int im = 0; im < 2; im++)
#pragma unroll
                for (int in = 0; in < 8; in++)
                    mma_tf32(acc[im][in], afr[im], bfr[in]);
        }
        __syncthreads();
    }

    const int g = lid >> 2, cq = lid & 3;
#pragma unroll
    for (int im = 0; im < 2; im++) {
        const int mbase = bm + warp_m * 32 + im * 16 + g;
#pragma unroll
        for (int in = 0; in < 8; in++) {
            const int n0 = bn + warp_n * 64 + in * 8 + cq * 2;
            const float c0 = acc[im][in][0], c1 = acc[im][in][1];
            const float c2 = acc[im][in][2], c3 = acc[im][in][3];
            if (EPI == 0) {
                const float2 bv = *(const float2*)(bias + n0);
                const int h = n0 >> 6, d = n0 & 63;
#pragma unroll
                for (int rr = 0; rr < 2; rr++) {
                    const int m = mbase + rr * 8;
                    const int b = m >> 11, s = m & 2047;
                    float2 o; o.x = (rr ? c2 : c0) + bv.x; o.y = (rr ? c3 : c1) + bv.y;
                    *(float2*)&C[(((size_t)(b * NUM_HEADS + h) * SEQ) + s) * D_K + d] = o;
                }
            } else if (EPI == 1) {
                const float b0 = bias[n0], b1 = bias[n0 + 1];
                const int h = n0 >> 6, d = n0 & 63;
#pragma unroll
                for (int rr = 0; rr < 2; rr++) {
                    const int m = mbase + rr * 8;
                    const int b = m >> 11, s = m & 2047;
                    const size_t base = ((size_t)(b * NUM_HEADS + h) * D_K + d) * SEQ + s;
                    C[base]       = (rr ? c2 : c0) + b0;
                    C[base + SEQ] = (rr ? c3 : c1) + b1;
                }
            } else {
                const float2 bv = *(const float2*)(bias + n0);
#pragma unroll
                for (int rr = 0; rr < 2; rr++) {
                    const int m = mbase + rr * 8;
                    float2 o; o.x = (rr ? c2 : c0) + bv.x; o.y = (rr ? c3 : c1) + bv.y;
                    *(float2*)&C[(size_t)m * D_MODEL + n0] = o;
                }
            }
        }
    }
}

// ---------------------------------------------------------------------------
// flashA v2: fused scores + exp + row-sum + ctx with REGISTER P (no P smem).
// Scores C-frags are shuffled in-register into A-frags for the ctx MMA.
// Each warp accumulates a k-partial ctx (32 rows x 64 d); warp_n pairs merge
// through smem once at the end.
// ---------------------------------------------------------------------------
#define FB_Q    0                        // Q frags: 64*ABLK = 8448
#define FB_K0   (64 * ABLK)              // 8448
#define FB_KB   (128 * BBLK)             // 8448 per K buffer
#define FB_V    (FB_K0 + 2 * FB_KB)      // 25344, V frags 128*BBLK = 8448
#define FB_X    FB_K0                    // exchange buffer (reuses K region)
#define XBLK    66
#define FB_PART (FB_V + 128 * BBLK)      // 33792
#define FB_LSUM (FB_PART + 256)          // 34048
#define FB_TOT  (FB_LSUM + 128)          // 34176 floats = 136704 B

__global__ void __launch_bounds__(256) flash_kernel()
{
    extern __shared__ float smf[];
    const int tid = threadIdx.x;
    const int wid = tid >> 5, lid = tid & 31;
    const int warp_m = wid >> 1, warp_n = wid & 1;
    const int g = lid >> 2, cq = lid & 3;
    const int bm = blockIdx.x * 128;
    const int bh = blockIdx.y;

    const float* qp = g_q + (size_t)bh * SEQ * D_K + (size_t)bm * D_K;
    const float* kp = g_k + (size_t)bh * SEQ * D_K;
    const float* vp = g_vt + (size_t)bh * D_K * SEQ;

    // ---- stage Q tile into A-frag layout (rows 128 x k 64) ----
#pragma unroll
    for (int it = 0; it < 8; it++) {
        int f = tid + it * 256;
        int row = f >> 4, c4 = f & 15;
        float4 v = *(const float4*)(qp + (size_t)row * D_K + c4 * 4);
        int ma = row >> 4, r = row & 15;
        int ka = c4 >> 1;
        int slot = ((c4 & 1) << 1) | (r >> 3);
        float* p = smf + FB_Q + ((ka * 8 + ma) * ABLK + ((r & 7) << 4) + slot);
        p[0]  = __uint_as_float(rn_tf32(v.x));
        p[4]  = __uint_as_float(rn_tf32(v.y));
        p[8]  = __uint_as_float(rn_tf32(v.z));
        p[12] = __uint_as_float(rn_tf32(v.w));
    }

    float4 rk[8];
    auto ldg_k = [&](int t) {
        const float* kb = kp + (size_t)(t * 128) * D_K;
#pragma unroll
        for (int it = 0; it < 8; it++) {
            int f = tid + it * 256;
            int row = f >> 4, c4 = f & 15;
            rk[it] = *(const float4*)(kb + (size_t)row * D_K + c4 * 4);
        }
    };
    auto sts_k = [&](int buf) {
        float* db = smf + FB_K0 + buf * FB_KB;
#pragma unroll
        for (int it = 0; it < 8; it++) {
            int f = tid + it * 256;
            int row = f >> 4, c4 = f & 15;
            int na = row >> 3, nn = row & 7;
            int ka = c4 >> 1, slot = c4 & 1;
            float* p = db + ((ka * 16 + na) * BBLK + (nn << 3) + slot);
            p[0] = __uint_as_float(rn_tf32(rk[it].x));
            p[2] = __uint_as_float(rn_tf32(rk[it].y));
            p[4] = __uint_as_float(rn_tf32(rk[it].z));
            p[6] = __uint_as_float(rn_tf32(rk[it].w));
        }
    };

    float4 rv[4];
    auto ldg_v = [&](int t, int half) {
        const float* vb = vp + t * 128;
#pragma unroll
        for (int it = 0; it < 4; it++) {
            int f = tid + (half * 4 + it) * 256;
            int row = f >> 5, c4 = f & 31;
            rv[it] = *(const float4*)(vb + (size_t)row * SEQ + c4 * 4);
        }
    };
    auto sts_v = [&](int half) {
#pragma unroll
        for (int it = 0; it < 4; it++) {
            int f = tid + (half * 4 + it) * 256;
            int row = f >> 5, c4 = f & 31;
            int na = row >> 3, nn = row & 7;
            int ka = c4 >> 1, slot = c4 & 1;
            float* p = smf + FB_V + ((ka * 8 + na) * BBLK + (nn << 3) + slot);
            p[0] = __uint_as_float(rn_tf32(rv[it].x));
            p[2] = __uint_as_float(rn_tf32(rv[it].y));
            p[4] = __uint_as_float(rn_tf32(rv[it].z));
            p[6] = __uint_as_float(rn_tf32(rv[it].w));
        }
    };

    // k-partial ctx accumulator: 32 rows x 64 d-cols per warp
    float acc2[2][8][4];
#pragma unroll
    for (int im = 0; im < 2; im++)
#pragma unroll
        for (int in = 0; in < 8; in++)
#pragma unroll
            for (int c = 0; c < 4; c++) acc2[im][in][c] = 0.f;
    float racc[2][2] = {{0.f, 0.f}, {0.f, 0.f}};

    // shuffle source lanes for C-frag -> A-frag conversion
    const int srcA = (lid & 28) | (cq >> 1);
    const int srcB = srcA + 2;
    const bool odd = (cq & 1);

    ldg_k(0); sts_k(0); ldg_k(1);
    __syncthreads();

    for (int t = 0; t < 16; t++) {
        if (t + 1 < 16) sts_k((t + 1) & 1);
        if (t + 2 < 16) ldg_k(t + 2);

        // ---- scores MMA: Q(128x64) x K_tile(128x64)^T ----
        float acc[2][8][4];
#pragma unroll
        for (int im = 0; im < 2; im++)
#pragma unroll
            for (int in = 0; in < 8; in++)
#pragma unroll
                for (int c = 0; c < 4; c++) acc[im][in][c] = 0.f;

        const float* Kd = smf + FB_K0 + (t & 1) * FB_KB;
#pragma unroll
        for (int ka = 0; ka < 8; ka++) {
            uint32_t afr[2][4];
#pragma unroll
            for (int im = 0; im < 2; im++) {
                const float4 v = *(const float4*)(smf + FB_Q + (ka * 8 + warp_m * 2 + im) * ABLK + lid * 4);
                afr[im][0] = __float_as_uint(v.x); afr[im][1] = __float_as_uint(v.y);
                afr[im][2] = __float_as_uint(v.z); afr[im][3] = __float_as_uint(v.w);
            }
            uint32_t bfr[8][2];
#pragma unroll
            for (int in = 0; in < 8; in++) {
                const float2 v = *(const float2*)(Kd + (ka * 16 + warp_n * 8 + in) * BBLK + lid * 2);
                bfr[in][0] = __float_as_uint(v.x); bfr[in][1] = __float_as_uint(v.y);
            }
#pragma unroll
            for (int im = 0; im < 2; im++)
#pragma unroll
                for (int in = 0; in < 8; in++)
                    mma_tf32(acc[im][in], afr[im], bfr[in]);
        }

        // ---- exp + row sums + in-register C-frag -> A-frag conversion ----
        // (V staging interleaved so its LDG latency hides under ALU/MUFU)
#pragma unroll
        for (int im = 0; im < 2; im++) {
            ldg_v(t, im);
#pragma unroll
            for (int in = 0; in < 8; in++) {
                const float e0 = rn_tf32f(__expf(acc[im][in][0] * 0.125f));
                const float e1 = rn_tf32f(__expf(acc[im][in][1] * 0.125f));
                const float e2 = rn_tf32f(__expf(acc[im][in][2] * 0.125f));
                const float e3 = rn_tf32f(__expf(acc[im][in][3] * 0.125f));
                racc[im][0] += e0 + e1;
                racc[im][1] += e2 + e3;
                // a0=(g,cq) a1=(g+8,cq) a2=(g,cq+4) a3=(g+8,cq+4)
                const float x0 = __shfl_sync(0xffffffffu, e0, srcA);
                const float x1 = __shfl_sync(0xffffffffu, e1, srcA);
                const float x2 = __shfl_sync(0xffffffffu, e2, srcA);
                const float x3 = __shfl_sync(0xffffffffu, e3, srcA);
                const float y0 = __shfl_sync(0xffffffffu, e0, srcB);
                const float y1 = __shfl_sync(0xffffffffu, e1, srcB);
                const float y2 = __shfl_sync(0xffffffffu, e2, srcB);
                const float y3 = __shfl_sync(0xffffffffu, e3, srcB);
                acc[im][in][0] = odd ? x1 : x0;
                acc[im][in][1] = odd ? x3 : x2;
                acc[im][in][2] = odd ? y1 : y0;
                acc[im][in][3] = odd ? y3 : y2;
            }
            sts_v(im);
        }
        __syncthreads();

        // ---- ctx MMA: warp's k-atoms = warp_n*8 + j (its 64 score cols) ----
#pragma unroll
        for (int j = 0; j < 8; j++) {
            const int kg = warp_n * 8 + j;
            uint32_t bfr[8][2];
#pragma unroll
            for (int nd = 0; nd < 8; nd++) {
                const float2 v = *(const float2*)(smf + FB_V + (kg * 8 + nd) * BBLK + lid * 2);
                bfr[nd][0] = __float_as_uint(v.x); bfr[nd][1] = __float_as_uint(v.y);
            }
#pragma unroll
            for (int im = 0; im < 2; im++) {
                uint32_t afr[4];
                afr[0] = __float_as_uint(acc[im][j][0]);
                afr[1] = __float_as_uint(acc[im][j][1]);
                afr[2] = __float_as_uint(acc[im][j][2]);
                afr[3] = __float_as_uint(acc[im][j][3]);
#pragma unroll
                for (int nd = 0; nd < 8; nd++)
                    mma_tf32(acc2[im][nd], afr, bfr[nd]);
            }
        }
        __syncthreads();
    }

    // ---- finalize row sums (deterministic reduction) ----
#pragma unroll
    for (int im = 0; im < 2; im++)
#pragma unroll
        for (int rr = 0; rr < 2; rr++) {
            float s = racc[im][rr];
            s += __shfl_xor_sync(0xffffffffu, s, 1);
            s += __shfl_xor_sync(0xffffffffu, s, 2);
            if (cq == 0)
                smf[FB_PART + warp_n * 128 + warp_m * 32 + im * 16 + rr * 8 + g] = s;
        }
    __syncthreads();
    if (tid < 128) {
        float l = smf[FB_PART + tid] + smf[FB_PART + 128 + tid];
        smf[FB_LSUM + tid] = l;
        g_l[(size_t)bh * SEQ + bm + tid] = l;
    }
    __syncthreads();

    // ---- merge warp_n k-partials through smem (reuses K region) ----
    if (warp_n == 1) {
#pragma unroll
        for (int im = 0; im < 2; im++)
#pragma unroll
            for (int in = 0; in < 8; in++) {
                const int row = im * 16 + g;
                const int col = in * 8 + cq * 2;
                float* base = smf + FB_X + warp_m * (32 * XBLK);
                *(float2*)(base + row * XBLK + col) =
                    make_float2(acc2[im][in][0], acc2[im][in][1]);
                *(float2*)(base + (row + 8) * XBLK + col) =
                    make_float2(acc2[im][in][2], acc2[im][in][3]);
            }
    }
    __syncthreads();

    if (warp_n == 0) {
        const int b = bh >> 4, h = bh & 15;
        const float* base = smf + FB_X + warp_m * (32 * XBLK);
#pragma unroll
        for (int im = 0; im < 2; im++)
#pragma unroll
            for (int rr = 0; rr < 2; rr++) {
                const int rowl = warp_m * 32 + im * 16 + g + rr * 8;
                const float inv = 1.f / smf[FB_LSUM + rowl];
                const int srow = bm + rowl;
#pragma unroll
                for (int in = 0; in < 8; in++) {
                    const int col = in * 8 + cq * 2;
                    const float2 p = *(const float2*)(base + (im * 16 + g + rr * 8) * XBLK + col);
                    float2 o;
                    o.x = (acc2[im][in][rr ? 2 : 0] + p.x) * inv;
                    o.y = (acc2[im][in][rr ? 3 : 1] + p.y) * inv;
                    *(float2*)&g_ctx[((size_t)(b * SEQ + srow)) * D_MODEL + h * D_K + col] = o;
                }
            }
    }
}

// ---------------------------------------------------------------------------
// attnW: recompute scores, write attn = exp(s/8) / l.  Write-once, streaming.
// ---------------------------------------------------------------------------
#define AW_Q   0
#define AW_K0  (64 * ABLK)
#define AW_KB  (128 * BBLK)
#define AW_INV (AW_K0 + 2 * AW_KB)
#define AW_TOT (AW_INV + 128)     // 25472 floats

__global__ void __launch_bounds__(256, 2) attnw_kernel(float* __restrict__ attn)
{
    extern __shared__ float smf[];
    const int tid = threadIdx.x;
    const int wid = tid >> 5, lid = tid & 31;
    const int warp_m = wid >> 1, warp_n = wid & 1;
    const int g = lid >> 2, cq = lid & 3;
    const int bm = blockIdx.x * 128;
    const int bh = blockIdx.y;

    const float* qp = g_q + (size_t)bh * SEQ * D_K + (size_t)bm * D_K;
    const float* kp = g_k + (size_t)bh * SEQ * D_K;
    float* ap = attn + (size_t)bh * SEQ * SEQ;

    if (tid < 128)
        smf[AW_INV + tid] = 1.f / g_l[(size_t)bh * SEQ + bm + tid];

#pragma unroll
    for (int it = 0; it < 8; it++) {
        int f = tid + it * 256;
        int row = f >> 4, c4 = f & 15;
        float4 v = *(const float4*)(qp + (size_t)row * D_K + c4 * 4);
        int ma = row >> 4, r = row & 15;
        int ka = c4 >> 1;
        int slot = ((c4 & 1) << 1) | (r >> 3);
        float* p = smf + AW_Q + ((ka * 8 + ma) * ABLK + ((r & 7) << 4) + slot);
        p[0]  = __uint_as_float(rn_tf32(v.x));
        p[4]  = __uint_as_float(rn_tf32(v.y));
        p[8]  = __uint_as_float(rn_tf32(v.z));
        p[12] = __uint_as_float(rn_tf32(v.w));
    }

    float4 rk[8];
    auto ldg_k = [&](int t) {
        const float* kb = kp + (size_t)(t * 128) * D_K;
#pragma unroll
        for (int it = 0; it < 8; it++) {
            int f = tid + it * 256;
            int row = f >> 4, c4 = f & 15;
            rk[it] = *(const float4*)(kb + (size_t)row * D_K + c4 * 4);
        }
    };
    auto sts_k = [&](int buf) {
        float* db = smf + AW_K0 + buf * AW_KB;
#pragma unroll
        for (int it = 0; it < 8; it++) {
            int f = tid + it * 256;
            int row = f >> 4, c4 = f & 15;
            int na = row >> 3, nn = row & 7;
            int ka = c4 >> 1, slot = c4 & 1;
            float* p = db + ((ka * 16 + na) * BBLK + (nn << 3) + slot);
            p[0] = __uint_as_float(rn_tf32(rk[it].x));
            p[2] = __uint_as_float(rn_tf32(rk[it].y));
            p[4] = __uint_as_float(rn_tf32(rk[it].z));
            p[6] = __uint_as_float(rn_tf32(rk[it].w));
        }
    };

    ldg_k(0); sts_k(0); ldg_k(1);
    __syncthreads();

    const int row0q = warp_m * 32 + g;
    const float inv0 = smf[AW_INV + row0q];
    const float inv8 = smf[AW_INV + row0q + 8];
    const float inv16 = smf[AW_INV + row0q + 16];
    const float inv24 = smf[AW_INV + row0q + 24];

    for (int t = 0; t < 16; t++) {
        if (t + 1 < 16) sts_k((t + 1) & 1);
        if (t + 2 < 16) ldg_k(t + 2);

        float acc[2][8][4];
#pragma unroll
        for (int im = 0; im < 2; im++)
#pragma unroll
            for (int in = 0; in < 8; in++)
#pragma unroll
                for (int c = 0; c < 4; c++) acc[im][in][c] = 0.f;

        const float* Kd = smf + AW_K0 + (t & 1) * AW_KB;
#pragma unroll
        for (int ka = 0; ka < 8; ka++) {
            uint32_t afr[2][4];
#pragma unroll
            for (int im = 0; im < 2; im++) {
                const float4 v = *(const float4*)(smf + AW_Q + (ka * 8 + warp_m * 2 + im) * ABLK + lid * 4);
                afr[im][0] = __float_as_uint(v.x); afr[im][1] = __float_as_uint(v.y);
                afr[im][2] = __float_as_uint(v.z); afr[im][3] = __float_as_uint(v.w);
            }
            uint32_t bfr[8][2];
#pragma unroll
            for (int in = 0; in < 8; in++) {
                const float2 v = *(const float2*)(Kd + (ka * 16 + warp_n * 8 + in) * BBLK + lid * 2);
                bfr[in][0] = __float_as_uint(v.x); bfr[in][1] = __float_as_uint(v.y);
            }
#pragma unroll
            for (int im = 0; im < 2; im++)
#pragma unroll
                for (int in = 0; in < 8; in++)
                    mma_tf32(acc[im][in], afr[im], bfr[in]);
        }

#pragma unroll
        for (int im = 0; im < 2; im++) {
            const int mrow = bm + warp_m * 32 + im * 16 + g;
            const float iv0 = im ? inv16 : inv0;
            const float iv1 = im ? inv24 : inv8;
#pragma unroll
            for (int in = 0; in < 8; in++) {
                const int n0 = t * 128 + warp_n * 64 + in * 8 + cq * 2;
                float2 o0, o1;
                o0.x = __expf(acc[im][in][0] * 0.125f) * iv0;
                o0.y = __expf(acc[im][in][1] * 0.125f) * iv0;
                o1.x = __expf(acc[im][in][2] * 0.125f) * iv1;
                o1.y = __expf(acc[im][in][3] * 0.125f) * iv1;
                __stcs((float2*)&ap[(size_t)mrow * SEQ + n0], o0);
                __stcs((float2*)&ap[(size_t)(mrow + 8) * SEQ + n0], o1);
            }
        }
        __syncthreads();
    }
}

extern "C" void kernel_launch(void* const* d_in, const int* in_sizes, int n_in,
                              void* d_out, int out_size) {
    const float* Q  = (const float*)d_in[0];
    const float* K  = (const float*)d_in[1];
    const float* V  = (const float*)d_in[2];
    const float* Wq = (const float*)d_in[3];
    const float* bq = (const float*)d_in[4];
    const float* Wk = (const float*)d_in[5];
    const float* bk = (const float*)d_in[6];
    const float* Wv = (const float*)d_in[7];
    const float* bv = (const float*)d_in[8];
    const float* Wo = (const float*)d_in[9];
    const float* bo = (const float*)d_in[10];

    float* out = (float*)d_out;

    const size_t OUT_ELEMS  = (size_t)M_ROWS * D_MODEL;
    const size_t ATTN_ELEMS = (size_t)BH * SEQ * SEQ;

    float* attn;
    if ((size_t)out_size >= OUT_ELEMS + ATTN_ELEMS) {
        attn = out + OUT_ELEMS;
    } else {
        void* p = nullptr;
        cudaGetSymbolAddress(&p, g_attn_fb);
        attn = (float*)p;
    }

    float *qp, *kp, *vtp, *cp;
    { void* t; cudaGetSymbolAddress(&t, g_q);   qp  = (float*)t; }
    { void* t; cudaGetSymbolAddress(&t, g_k);   kp  = (float*)t; }
    { void* t; cudaGetSymbolAddress(&t, g_vt);  vtp = (float*)t; }
    { void* t; cudaGetSymbolAddress(&t, g_ctx); cp  = (float*)t; }

    const int SMP  = (2 * 32 * ABLK + 2 * 64 * BBLK) * 4;  // proj smem bytes
    const int SMFA = FB_TOT * 4;
    const int SMAW = AW_TOT * 4;

    cudaFuncSetAttribute(mma_gemm<0>, cudaFuncAttributeMaxDynamicSharedMemorySize, SMP);
    cudaFuncSetAttribute(mma_gemm<1>, cudaFuncAttributeMaxDynamicSharedMemorySize, SMP);
    cudaFuncSetAttribute(mma_gemm<2>, cudaFuncAttributeMaxDynamicSharedMemorySize, SMP);
    cudaFuncSetAttribute(flash_kernel, cudaFuncAttributeMaxDynamicSharedMemorySize, SMFA);
    cudaFuncSetAttribute(attnw_kernel, cudaFuncAttributeMaxDynamicSharedMemorySize, SMAW);

    dim3 projGrid(D_MODEL / 128, M_ROWS / 128);     // (8, 64)
    mma_gemm<0><<<projGrid, 256, SMP>>>(Q, Wq, bq, qp, 1024, 1024, 1024);
    mma_gemm<0><<<projGrid, 256, SMP>>>(K, Wk, bk, kp, 1024, 1024, 1024);
    mma_gemm<1><<<projGrid, 256, SMP>>>(V, Wv, bv, vtp, 1024, 1024, 1024);

    dim3 attGrid(SEQ / 128, BH);                    // (16, 64)
    flash_kernel<<<attGrid, 256, SMFA>>>();
    attnw_kernel<<<attGrid, 256, SMAW>>>(attn);

    mma_gemm<2><<<projGrid, 256, SMP>>>(cp, Wo, bo, out, 1024, 1024, 1024);
}

// round 7
// speedup vs baseline: 1.0416x; 1.0416x over previous
#include <cuda_runtime.h>
#include <cstdint>

#define D_MODEL 1024
#define NUM_HEADS 16
#define D_K 64
#define BATCH 4
#define SEQ 2048
#define BH (BATCH * NUM_HEADS)          // 64
#define M_ROWS (BATCH * SEQ)            // 8192

// Scratch (device globals; no dynamic allocation allowed)
__device__ float g_q[(size_t)BH * SEQ * D_K];
__device__ float g_k[(size_t)BH * SEQ * D_K];
__device__ float g_vt[(size_t)BH * D_K * SEQ];   // V transposed: [bh][d][s]
__device__ float g_ctx[(size_t)M_ROWS * D_MODEL];
__device__ float g_l[(size_t)BH * SEQ];          // softmax row sums
__device__ float g_attn_fb[(size_t)BH * SEQ * SEQ];

// Round fp32 -> tf32 (round-to-nearest; HMMA then truncates losslessly)
__device__ __forceinline__ uint32_t rn_tf32(float x) {
    return (__float_as_uint(x) + 0x1000u) & 0xFFFFE000u;
}

__device__ __forceinline__ void mma_tf32(float* d, const uint32_t* a, const uint32_t* b) {
    asm volatile(
        "mma.sync.aligned.m16n8k8.row.col.f32.tf32.tf32.f32 "
        "{%0,%1,%2,%3}, {%4,%5,%6,%7}, {%8,%9}, {%0,%1,%2,%3};"
        : "+f"(d[0]), "+f"(d[1]), "+f"(d[2]), "+f"(d[3])
        : "r"(a[0]), "r"(a[1]), "r"(a[2]), "r"(a[3]), "r"(b[0]), "r"(b[1]));
}

// Fragment smem block strides (padded to break STS bank conflicts)
#define ABLK 132   // 128 floats + 4 pad
#define BBLK 66    // 64 floats + 2 pad

// ---------------------------------------------------------------------------
// Projection GEMM:  C = A(M x K, K-major) * B(N x K, K-major)^T   (tf32 MMA)
// Block tile 128 x 128, BK = 32, 256 threads, warps 4x2, 2 CTAs/SM.
// EPI: 0 = split-heads Q/K (+bias), 1 = V transposed (+bias), 2 = row-major (+bias)
// ---------------------------------------------------------------------------
template <int EPI>
__global__ void __launch_bounds__(256, 2) mma_gemm(
    const float* __restrict__ A, const float* __restrict__ B,
    const float* __restrict__ bias, float* __restrict__ C,
    int K, int lda, int ldb)
{
    constexpr int A_FLOATS = 32 * ABLK;   // ka4 x ma8 blocks
    constexpr int B_FLOATS = 64 * BBLK;   // ka4 x na16 blocks

    extern __shared__ float smf[];
    float* As = smf;
    float* Bs = smf + 2 * A_FLOATS;

    const int tid = threadIdx.x;
    const int wid = tid >> 5, lid = tid & 31;
    const int warp_m = wid >> 1, warp_n = wid & 1;
    const int bm = blockIdx.y * 128;
    const int bn = blockIdx.x * 128;

    const float* Ab = A + (size_t)bm * lda;
    const float* Bb = B + (size_t)bn * ldb;

    float4 ra[4], rb[4];

    auto ldg_tiles = [&](int k0) {
#pragma unroll
        for (int it = 0; it < 4; it++) {
            int f = tid + it * 256;
            int row = f >> 3, k4 = f & 7;
            ra[it] = *(const float4*)(Ab + (size_t)row * lda + k0 + k4 * 4);
            rb[it] = *(const float4*)(Bb + (size_t)row * ldb + k0 + k4 * 4);
        }
    };

    auto sts_tiles = [&](int buf) {
        float* da = As + buf * A_FLOATS;
        float* db = Bs + buf * B_FLOATS;
#pragma unroll
        for (int it = 0; it < 4; it++) {
            int f = tid + it * 256;
            int row = f >> 3, k4 = f & 7;
            {
                int ma = row >> 4, r = row & 15;
                int ka = k4 >> 1;
                int slot = ((k4 & 1) << 1) | (r >> 3);
                float* p = da + ((ka * 8 + ma) * ABLK + ((r & 7) << 4) + slot);
                p[0]  = __uint_as_float(rn_tf32(ra[it].x));
                p[4]  = __uint_as_float(rn_tf32(ra[it].y));
                p[8]  = __uint_as_float(rn_tf32(ra[it].z));
                p[12] = __uint_as_float(rn_tf32(ra[it].w));
            }
            {
                int na = row >> 3, nn = row & 7;
                int ka = k4 >> 1;
                int slot = k4 & 1;
                float* p = db + ((ka * 16 + na) * BBLK + (nn << 3) + slot);
                p[0] = __uint_as_float(rn_tf32(rb[it].x));
                p[2] = __uint_as_float(rn_tf32(rb[it].y));
                p[4] = __uint_as_float(rn_tf32(rb[it].z));
                p[6] = __uint_as_float(rn_tf32(rb[it].w));
            }
        }
    };

    float acc[2][8][4];
#pragma unroll
    for (int im = 0; im < 2; im++)
#pragma unroll
        for (int in = 0; in < 8; in++)
#pragma unroll
            for (int c = 0; c < 4; c++) acc[im][in][c] = 0.f;

    const int KS = K >> 5;
    ldg_tiles(0);
    sts_tiles(0);
    ldg_tiles(32);
    __syncthreads();

    for (int ks = 0; ks < KS; ks++) {
        if (ks + 1 < KS) sts_tiles((ks + 1) & 1);
        if (ks + 2 < KS) ldg_tiles((ks + 2) << 5);

        const float* Ad = As + (ks & 1) * A_FLOATS;
        const float* Bd = Bs + (ks & 1) * B_FLOATS;
#pragma unroll
        for (int ka = 0; ka < 4; ka++) {
            uint32_t afr[2][4];
#pragma unroll
            for (int im = 0; im < 2; im++) {
                const float4 v = *(const float4*)(Ad + (ka * 8 + warp_m * 2 + im) * ABLK + lid * 4);
                afr[im][0] = __float_as_uint(v.x); afr[im][1] = __float_as_uint(v.y);
                afr[im][2] = __float_as_uint(v.z); afr[im][3] = __float_as_uint(v.w);
            }
            uint32_t bfr[8][2];
#pragma unroll
            for (int in = 0; in < 8; in++) {
                const float2 v = *(const float2*)(Bd + (ka * 16 + warp_n * 8 + in) * BBLK + lid * 2);
                bfr[in][0] = __float_as_uint(v.x); bfr[in][1] = __float_as_uint(v.y);
            }
#pragma unroll
            for (int im = 0; im < 2; im++)
#pragma unroll
                for (int in = 0; in < 8; in++)
                    mma_tf32(acc[im][in], afr[im], bfr[in]);
        }
        __syncthreads();
    }

    const int g = lid >> 2, cq = lid & 3;
#pragma unroll
    for (int im = 0; im < 2; im++) {
        const int mbase = bm + warp_m * 32 + im * 16 + g;
#pragma unroll
        for (int in = 0; in < 8; in++) {
            const int n0 = bn + warp_n * 64 + in * 8 + cq * 2;
            const float c0 = acc[im][in][0], c1 = acc[im][in][1];
            const float c2 = acc[im][in][2], c3 = acc[im][in][3];
            if (EPI == 0) {
                const float2 bv = *(const float2*)(bias + n0);
                const int h = n0 >> 6, d = n0 & 63;
#pragma unroll
                for (int rr = 0; rr < 2; rr++) {
                    const int m = mbase + rr * 8;
                    const int b = m >> 11, s = m & 2047;
                    float2 o; o.x = (rr ? c2 : c0) + bv.x; o.y = (rr ? c3 : c1) + bv.y;
                    *(float2*)&C[(((size_t)(b * NUM_HEADS + h) * SEQ) + s) * D_K + d] = o;
                }
            } else if (EPI == 1) {
                const float b0 = bias[n0], b1 = bias[n0 + 1];
                const int h = n0 >> 6, d = n0 & 63;
#pragma unroll
                for (int rr = 0; rr < 2; rr++) {
                    const int m = mbase + rr * 8;
                    const int b = m >> 11, s = m & 2047;
                    const size_t base = ((size_t)(b * NUM_HEADS + h) * D_K + d) * SEQ + s;
                    C[base]       = (rr ? c2 : c0) + b0;
                    C[base + SEQ] = (rr ? c3 : c1) + b1;
                }
            } else {
                const float2 bv = *(const float2*)(bias + n0);
#pragma unroll
                for (int rr = 0; rr < 2; rr++) {
                    const int m = mbase + rr * 8;
                    float2 o; o.x = (rr ? c2 : c0) + bv.x; o.y = (rr ? c3 : c1) + bv.y;
                    *(float2*)&C[(size_t)m * D_MODEL + n0] = o;
                }
            }
        }
    }
}

// ---------------------------------------------------------------------------
// flashA v3: fused scores + exp + row-sum + ctx, 512 threads (16 warps).
// Scores: warp grid 4m x 4n, warp tile 32x32. ctx: warp tile 32 rows x 16 d.
// P goes through smem in A-frag layout (float2 stores, conflict-padded).
// ---------------------------------------------------------------------------
#define FB_Q    0                        // Q frags: 64*ABLK = 8448
#define FB_K0   (64 * ABLK)              // 8448
#define FB_KB   (128 * BBLK)             // 8448 per K buffer
#define FB_P    (FB_K0 + 2 * FB_KB)      // 25344, P frags 128*ABLK = 16896
#define FB_V    (FB_P + 128 * ABLK)      // 42240, V frags 128*BBLK = 8448
#define FB_PART (FB_V + 128 * BBLK)      // 50688 (4 x 128)
#define FB_LSUM (FB_PART + 512)          // 51200
#define FB_TOT  (FB_LSUM + 128)          // 51328 floats = 205312 B

__global__ void __launch_bounds__(512) flash_kernel()
{
    extern __shared__ float smf[];
    const int tid = threadIdx.x;
    const int wid = tid >> 5, lid = tid & 31;
    const int warp_m = wid >> 2, warp_n = wid & 3;   // 4 x 4 warp grid
    const int g = lid >> 2, cq = lid & 3;
    const int bm = blockIdx.x * 128;
    const int bh = blockIdx.y;

    const float* qp = g_q + (size_t)bh * SEQ * D_K + (size_t)bm * D_K;
    const float* kp = g_k + (size_t)bh * SEQ * D_K;
    const float* vp = g_vt + (size_t)bh * D_K * SEQ;

    // ---- stage Q tile into A-frag layout (rows 128 x k 64) ----
#pragma unroll
    for (int it = 0; it < 4; it++) {
        int f = tid + it * 512;
        int row = f >> 4, c4 = f & 15;
        float4 v = *(const float4*)(qp + (size_t)row * D_K + c4 * 4);
        int ma = row >> 4, r = row & 15;
        int ka = c4 >> 1;
        int slot = ((c4 & 1) << 1) | (r >> 3);
        float* p = smf + FB_Q + ((ka * 8 + ma) * ABLK + ((r & 7) << 4) + slot);
        p[0]  = __uint_as_float(rn_tf32(v.x));
        p[4]  = __uint_as_float(rn_tf32(v.y));
        p[8]  = __uint_as_float(rn_tf32(v.z));
        p[12] = __uint_as_float(rn_tf32(v.w));
    }

    float4 rk[4];
    auto ldg_k = [&](int t) {
        const float* kb = kp + (size_t)(t * 128) * D_K;
#pragma unroll
        for (int it = 0; it < 4; it++) {
            int f = tid + it * 512;
            int row = f >> 4, c4 = f & 15;
            rk[it] = *(const float4*)(kb + (size_t)row * D_K + c4 * 4);
        }
    };
    auto sts_k = [&](int buf) {
        float* db = smf + FB_K0 + buf * FB_KB;
#pragma unroll
        for (int it = 0; it < 4; it++) {
            int f = tid + it * 512;
            int row = f >> 4, c4 = f & 15;
            int na = row >> 3, nn = row & 7;
            int ka = c4 >> 1, slot = c4 & 1;
            float* p = db + ((ka * 16 + na) * BBLK + (nn << 3) + slot);
            p[0] = __uint_as_float(rn_tf32(rk[it].x));
            p[2] = __uint_as_float(rn_tf32(rk[it].y));
            p[4] = __uint_as_float(rn_tf32(rk[it].z));
            p[6] = __uint_as_float(rn_tf32(rk[it].w));
        }
    };

    float4 rv[2];
    auto ldg_v = [&](int t, int half) {
        const float* vb = vp + t * 128;
#pragma unroll
        for (int it = 0; it < 2; it++) {
            int f = tid + (half * 2 + it) * 512;
            int row = f >> 5, c4 = f & 31;
            rv[it] = *(const float4*)(vb + (size_t)row * SEQ + c4 * 4);
        }
    };
    auto sts_v = [&](int half) {
#pragma unroll
        for (int it = 0; it < 2; it++) {
            int f = tid + (half * 2 + it) * 512;
            int row = f >> 5, c4 = f & 31;
            int na = row >> 3, nn = row & 7;
            int ka = c4 >> 1, slot = c4 & 1;
            float* p = smf + FB_V + ((ka * 8 + na) * BBLK + (nn << 3) + slot);
            p[0] = __uint_as_float(rn_tf32(rv[it].x));
            p[2] = __uint_as_float(rn_tf32(rv[it].y));
            p[4] = __uint_as_float(rn_tf32(rv[it].z));
            p[6] = __uint_as_float(rn_tf32(rv[it].w));
        }
    };

    // ctx accumulator: warp tile 32 rows x 16 d-cols
    float acc2[2][2][4];
#pragma unroll
    for (int im = 0; im < 2; im++)
#pragma unroll
        for (int in = 0; in < 2; in++)
#pragma unroll
            for (int c = 0; c < 4; c++) acc2[im][in][c] = 0.f;
    float racc[2][2] = {{0.f, 0.f}, {0.f, 0.f}};

    ldg_k(0); sts_k(0); ldg_k(1);
    __syncthreads();

    for (int t = 0; t < 16; t++) {
        if (t + 1 < 16) sts_k((t + 1) & 1);
        if (t + 2 < 16) ldg_k(t + 2);

        // ---- scores MMA: warp tile 32 rows x 32 cols ----
        float acc[2][4][4];
#pragma unroll
        for (int im = 0; im < 2; im++)
#pragma unroll
            for (int in = 0; in < 4; in++)
#pragma unroll
                for (int c = 0; c < 4; c++) acc[im][in][c] = 0.f;

        const float* Kd = smf + FB_K0 + (t & 1) * FB_KB;
#pragma unroll
        for (int ka = 0; ka < 8; ka++) {
            uint32_t afr[2][4];
#pragma unroll
            for (int im = 0; im < 2; im++) {
                const float4 v = *(const float4*)(smf + FB_Q + (ka * 8 + warp_m * 2 + im) * ABLK + lid * 4);
                afr[im][0] = __float_as_uint(v.x); afr[im][1] = __float_as_uint(v.y);
                afr[im][2] = __float_as_uint(v.z); afr[im][3] = __float_as_uint(v.w);
            }
            uint32_t bfr[4][2];
#pragma unroll
            for (int in = 0; in < 4; in++) {
                const float2 v = *(const float2*)(Kd + (ka * 16 + warp_n * 4 + in) * BBLK + lid * 2);
                bfr[in][0] = __float_as_uint(v.x); bfr[in][1] = __float_as_uint(v.y);
            }
#pragma unroll
            for (int im = 0; im < 2; im++)
#pragma unroll
                for (int in = 0; in < 4; in++)
                    mma_tf32(acc[im][in], afr[im], bfr[in]);
        }

        // ---- e = exp(s/8); row sums; float2 scatter to P-frag ----
        // Interleave V LDG halves so scatter ALU covers LDG latency.
#pragma unroll
        for (int im = 0; im < 2; im++) {
            ldg_v(t, im);
            const int row_blk = warp_m * 2 + im;           // 16-row block idx
#pragma unroll
            for (int in = 0; in < 4; in++) {
                const int col0 = warp_n * 32 + in * 8 + cq * 2;
#pragma unroll
                for (int j2 = 0; j2 < 2; j2++) {
                    const int col = col0 + j2;
                    const float e0 = __expf(acc[im][in][j2] * 0.125f);
                    const float e1 = __expf(acc[im][in][2 + j2] * 0.125f);
                    racc[im][0] += e0;
                    racc[im][1] += e1;
                    const int kk = col & 7;
                    const int word = ((col >> 3) * 8 + row_blk) * ABLK +
                                     g * 16 + (kk & 3) * 4 + ((kk >> 2) << 1);
                    float2 o; o.x = __uint_as_float(rn_tf32(e0));
                    o.y = __uint_as_float(rn_tf32(e1));
                    *(float2*)(smf + FB_P + word) = o;
                }
            }
            sts_v(im);
        }
        __syncthreads();

        // ---- ctx MMA: warp tile 32 rows x 16 d, k = 128 (16 atoms) ----
#pragma unroll
        for (int kg = 0; kg < 16; kg++) {
            uint32_t afr[2][4];
#pragma unroll
            for (int im = 0; im < 2; im++) {
                const float4 v = *(const float4*)(smf + FB_P + (kg * 8 + warp_m * 2 + im) * ABLK + lid * 4);
                afr[im][0] = __float_as_uint(v.x); afr[im][1] = __float_as_uint(v.y);
                afr[im][2] = __float_as_uint(v.z); afr[im][3] = __float_as_uint(v.w);
            }
#pragma unroll
            for (int in = 0; in < 2; in++) {
                uint32_t bfr[2];
                const float2 v = *(const float2*)(smf + FB_V + (kg * 8 + warp_n * 2 + in) * BBLK + lid * 2);
                bfr[0] = __float_as_uint(v.x); bfr[1] = __float_as_uint(v.y);
#pragma unroll
                for (int im = 0; im < 2; im++)
                    mma_tf32(acc2[im][in], afr[im], bfr);
            }
        }
        __syncthreads();
    }

    // ---- finalize row sums (deterministic reduction) ----
#pragma unroll
    for (int im = 0; im < 2; im++)
#pragma unroll
        for (int rr = 0; rr < 2; rr++) {
            float s = racc[im][rr];
            s += __shfl_xor_sync(0xffffffffu, s, 1);
            s += __shfl_xor_sync(0xffffffffu, s, 2);
            if (cq == 0)
                smf[FB_PART + warp_n * 128 + warp_m * 32 + im * 16 + rr * 8 + g] = s;
        }
    __syncthreads();
    if (tid < 128) {
        float l = smf[FB_PART + tid] + smf[FB_PART + 128 + tid] +
                  smf[FB_PART + 256 + tid] + smf[FB_PART + 384 + tid];
        smf[FB_LSUM + tid] = l;
        g_l[(size_t)bh * SEQ + bm + tid] = l;
    }
    __syncthreads();

    // ---- ctx epilogue: scale by 1/l, scatter to g_ctx ----
    const int b = bh >> 4, h = bh & 15;
#pragma unroll
    for (int im = 0; im < 2; im++) {
#pragma unroll
        for (int rr = 0; rr < 2; rr++) {
            const int rowl = warp_m * 32 + im * 16 + g + rr * 8;
            const float inv = 1.f / smf[FB_LSUM + rowl];
            const int srow = bm + rowl;
#pragma unroll
            for (int in = 0; in < 2; in++) {
                const int n0 = warp_n * 16 + in * 8 + cq * 2;
                float2 o;
                o.x = acc2[im][in][rr ? 2 : 0] * inv;
                o.y = acc2[im][in][rr ? 3 : 1] * inv;
                *(float2*)&g_ctx[((size_t)(b * SEQ + srow)) * D_MODEL + h * D_K + n0] = o;
            }
        }
    }
}

// ---------------------------------------------------------------------------
// attnW: recompute scores, write attn = exp(s/8) / l.  Write-once, streaming.
// ---------------------------------------------------------------------------
#define AW_Q   0
#define AW_K0  (64 * ABLK)
#define AW_KB  (128 * BBLK)
#define AW_INV (AW_K0 + 2 * AW_KB)
#define AW_TOT (AW_INV + 128)     // 25472 floats

__global__ void __launch_bounds__(256, 2) attnw_kernel(float* __restrict__ attn)
{
    extern __shared__ float smf[];
    const int tid = threadIdx.x;
    const int wid = tid >> 5, lid = tid & 31;
    const int warp_m = wid >> 1, warp_n = wid & 1;
    const int g = lid >> 2, cq = lid & 3;
    const int bm = blockIdx.x * 128;
    const int bh = blockIdx.y;

    const float* qp = g_q + (size_t)bh * SEQ * D_K + (size_t)bm * D_K;
    const float* kp = g_k + (size_t)bh * SEQ * D_K;
    float* ap = attn + (size_t)bh * SEQ * SEQ;

    if (tid < 128)
        smf[AW_INV + tid] = 1.f / g_l[(size_t)bh * SEQ + bm + tid];

#pragma unroll
    for (int it = 0; it < 8; it++) {
        int f = tid + it * 256;
        int row = f >> 4, c4 = f & 15;
        float4 v = *(const float4*)(qp + (size_t)row * D_K + c4 * 4);
        int ma = row >> 4, r = row & 15;
        int ka = c4 >> 1;
        int slot = ((c4 & 1) << 1) | (r >> 3);
        float* p = smf + AW_Q + ((ka * 8 + ma) * ABLK + ((r & 7) << 4) + slot);
        p[0]  = __uint_as_float(rn_tf32(v.x));
        p[4]  = __uint_as_float(rn_tf32(v.y));
        p[8]  = __uint_as_float(rn_tf32(v.z));
        p[12] = __uint_as_float(rn_tf32(v.w));
    }

    float4 rk[8];
    auto ldg_k = [&](int t) {
        const float* kb = kp + (size_t)(t * 128) * D_K;
#pragma unroll
        for (int it = 0; it < 8; it++) {
            int f = tid + it * 256;
            int row = f >> 4, c4 = f & 15;
            rk[it] = *(const float4*)(kb + (size_t)row * D_K + c4 * 4);
        }
    };
    auto sts_k = [&](int buf) {
        float* db = smf + AW_K0 + buf * AW_KB;
#pragma unroll
        for (int it = 0; it < 8; it++) {
            int f = tid + it * 256;
            int row = f >> 4, c4 = f & 15;
            int na = row >> 3, nn = row & 7;
            int ka = c4 >> 1, slot = c4 & 1;
            float* p = db + ((ka * 16 + na) * BBLK + (nn << 3) + slot);
            p[0] = __uint_as_float(rn_tf32(rk[it].x));
            p[2] = __uint_as_float(rn_tf32(rk[it].y));
            p[4] = __uint_as_float(rn_tf32(rk[it].z));
            p[6] = __uint_as_float(rn_tf32(rk[it].w));
        }
    };

    ldg_k(0); sts_k(0); ldg_k(1);
    __syncthreads();

    const int row0q = warp_m * 32 + g;
    const float inv0 = smf[AW_INV + row0q];
    const float inv8 = smf[AW_INV + row0q + 8];
    const float inv16 = smf[AW_INV + row0q + 16];
    const float inv24 = smf[AW_INV + row0q + 24];

    for (int t = 0; t < 16; t++) {
        if (t + 1 < 16) sts_k((t + 1) & 1);
        if (t + 2 < 16) ldg_k(t + 2);

        float acc[2][8][4];
#pragma unroll
        for (int im = 0; im < 2; im++)
#pragma unroll
            for (int in = 0; in < 8; in++)
#pragma unroll
                for (int c = 0; c < 4; c++) acc[im][in][c] = 0.f;

        const float* Kd = smf + AW_K0 + (t & 1) * AW_KB;
#pragma unroll
        for (int ka = 0; ka < 8; ka++) {
            uint32_t afr[2][4];
#pragma unroll
            for (int im = 0; im < 2; im++) {
                const float4 v = *(const float4*)(smf + AW_Q + (ka * 8 + warp_m * 2 + im) * ABLK + lid * 4);
                afr[im][0] = __float_as_uint(v.x); afr[im][1] = __float_as_uint(v.y);
                afr[im][2] = __float_as_uint(v.z); afr[im][3] = __float_as_uint(v.w);
            }
            uint32_t bfr[8][2];
#pragma unroll
            for (int in = 0; in < 8; in++) {
                const float2 v = *(const float2*)(Kd + (ka * 16 + warp_n * 8 + in) * BBLK + lid * 2);
                bfr[in][0] = __float_as_uint(v.x); bfr[in][1] = __float_as_uint(v.y);
            }
#pragma unroll
            for (int im = 0; im < 2; im++)
#pragma unroll
                for (int in = 0; in < 8; in++)
                    mma_tf32(acc[im][in], afr[im], bfr[in]);
        }

#pragma unroll
        for (int im = 0; im < 2; im++) {
            const int mrow = bm + warp_m * 32 + im * 16 + g;
            const float iv0 = im ? inv16 : inv0;
            const float iv1 = im ? inv24 : inv8;
#pragma unroll
            for (int in = 0; in < 8; in++) {
                const int n0 = t * 128 + warp_n * 64 + in * 8 + cq * 2;
                float2 o0, o1;
                o0.x = __expf(acc[im][in][0] * 0.125f) * iv0;
                o0.y = __expf(acc[im][in][1] * 0.125f) * iv0;
                o1.x = __expf(acc[im][in][2] * 0.125f) * iv1;
                o1.y = __expf(acc[im][in][3] * 0.125f) * iv1;
                __stcs((float2*)&ap[(size_t)mrow * SEQ + n0], o0);
                __stcs((float2*)&ap[(size_t)(mrow + 8) * SEQ + n0], o1);
            }
        }
        __syncthreads();
    }
}

extern "C" void kernel_launch(void* const* d_in, const int* in_sizes, int n_in,
                              void* d_out, int out_size) {
    const float* Q  = (const float*)d_in[0];
    const float* K  = (const float*)d_in[1];
    const float* V  = (const float*)d_in[2];
    const float* Wq = (const float*)d_in[3];
    const float* bq = (const float*)d_in[4];
    const float* Wk = (const float*)d_in[5];
    const float* bk = (const float*)d_in[6];
    const float* Wv = (const float*)d_in[7];
    const float* bv = (const float*)d_in[8];
    const float* Wo = (const float*)d_in[9];
    const float* bo = (const float*)d_in[10];

    float* out = (float*)d_out;

    const size_t OUT_ELEMS  = (size_t)M_ROWS * D_MODEL;
    const size_t ATTN_ELEMS = (size_t)BH * SEQ * SEQ;

    float* attn;
    if ((size_t)out_size >= OUT_ELEMS + ATTN_ELEMS) {
        attn = out + OUT_ELEMS;
    } else {
        void* p = nullptr;
        cudaGetSymbolAddress(&p, g_attn_fb);
        attn = (float*)p;
    }

    float *qp, *kp, *vtp, *cp;
    { void* t; cudaGetSymbolAddress(&t, g_q);   qp  = (float*)t; }
    { void* t; cudaGetSymbolAddress(&t, g_k);   kp  = (float*)t; }
    { void* t; cudaGetSymbolAddress(&t, g_vt);  vtp = (float*)t; }
    { void* t; cudaGetSymbolAddress(&t, g_ctx); cp  = (float*)t; }

    const int SMP  = (2 * 32 * ABLK + 2 * 64 * BBLK) * 4;  // proj smem bytes
    const int SMFA = FB_TOT * 4;
    const int SMAW = AW_TOT * 4;

    cudaFuncSetAttribute(mma_gemm<0>, cudaFuncAttributeMaxDynamicSharedMemorySize, SMP);
    cudaFuncSetAttribute(mma_gemm<1>, cudaFuncAttributeMaxDynamicSharedMemorySize, SMP);
    cudaFuncSetAttribute(mma_gemm<2>, cudaFuncAttributeMaxDynamicSharedMemorySize, SMP);
    cudaFuncSetAttribute(flash_kernel, cudaFuncAttributeMaxDynamicSharedMemorySize, SMFA);
    cudaFuncSetAttribute(attnw_kernel, cudaFuncAttributeMaxDynamicSharedMemorySize, SMAW);

    dim3 projGrid(D_MODEL / 128, M_ROWS / 128);     // (8, 64)
    mma_gemm<0><<<projGrid, 256, SMP>>>(Q, Wq, bq, qp, 1024, 1024, 1024);
    mma_gemm<0><<<projGrid, 256, SMP>>>(K, Wk, bk, kp, 1024, 1024, 1024);
    mma_gemm<1><<<projGrid, 256, SMP>>>(V, Wv, bv, vtp, 1024, 1024, 1024);

    dim3 attGrid(SEQ / 128, BH);                    // (16, 64)
    flash_kernel<<<attGrid, 512, SMFA>>>();
    attnw_kernel<<<attGrid, 256, SMAW>>>(attn);

    mma_gemm<2><<<projGrid, 256, SMP>>>(cp, Wo, bo, out, 1024, 1024, 1024);
}